// round 4
// baseline (speedup 1.0000x reference)
#include <cuda_runtime.h>

#define D      1024
#define BATCH  64
#define KSPLIT 16
#define KSLICE (D / KSPLIT)      // 64
#define NTILES (D / 64)          // 16
#define LOG2E  1.4426950408889634f
#define LN2    0.6931471805599453f

// ---------------- scratch (no allocations allowed) ----------------
__device__ __align__(16) float g_xl[BATCH * D];
__device__ __align__(16) float g_bl[BATCH * D];
__device__ __align__(16) float g_xs[BATCH * D];
__device__ __align__(16) float g_h1[BATCH * D];
__device__ __align__(16) float g_h2[BATCH * D];
__device__ __align__(16) float g_part[KSPLIT * BATCH * D];
__device__ unsigned g_cnt[2][NTILES];

__device__ __forceinline__ float ex2f(float x) {
    float r;
    asm("ex2.approx.ftz.f32 %0, %1;" : "=f"(r) : "f"(x));
    return r;
}

// packed f32x2 FMA (sm_100+): acc = a*b + acc, two fp32 lanes per instruction
__device__ __forceinline__ void ffma2(unsigned long long& acc,
                                      unsigned long long a,
                                      unsigned long long b) {
    asm("fma.rn.f32x2 %0, %1, %2, %3;" : "=l"(acc) : "l"(a), "l"(b), "l"(acc));
}

// ---------------- kernel 1: per-row bitonic sort + prefix-sum Bsum ----------------
__global__ void __launch_bounds__(D) sort_kernel(const float* __restrict__ x) {
    int row = blockIdx.x;
    int tid = threadIdx.x;
    __shared__ __align__(16) float sv[D];
    __shared__ float wsum[32];

    sv[tid] = x[row * D + tid];
    __syncthreads();

    for (int k = 2; k <= D; k <<= 1) {
        for (int j = k >> 1; j > 0; j >>= 1) {
            int ixj = tid ^ j;
            if (ixj > tid) {
                float a = sv[tid], b = sv[ixj];
                bool up = ((tid & k) == 0);
                if ((a > b) == up) { sv[tid] = b; sv[ixj] = a; }
            }
            __syncthreads();
        }
    }

    float v = sv[tid];
    int lane = tid & 31, wid = tid >> 5;
    float p = v;
#pragma unroll
    for (int off = 1; off < 32; off <<= 1) {
        float n = __shfl_up_sync(0xffffffffu, p, off);
        if (lane >= off) p += n;
    }
    if (lane == 31) wsum[wid] = p;
    __syncthreads();
    if (wid == 0) {
        float w = wsum[lane];
#pragma unroll
        for (int off = 1; off < 32; off <<= 1) {
            float n = __shfl_up_sync(0xffffffffu, w, off);
            if (lane >= off) w += n;
        }
        wsum[lane] = w;
    }
    __syncthreads();
    float S    = wsum[31];
    float pinc = p + (wid ? wsum[wid - 1] : 0.f);
    float bs   = (float)(2 * tid - D) * v + S - 2.f * (pinc - v);
    g_xl[row * D + tid] = v * LOG2E;
    g_bl[row * D + tid] = bs * LOG2E;
}

// ---------------- kernel 2: windowed soft-sort, unroll-4 ----------------
__global__ void __launch_bounds__(256) softsort_kernel() {
    int row = blockIdx.y;
    int i   = blockIdx.x * blockDim.x + threadIdx.x;
    __shared__ __align__(16) float sxl[D];
    __shared__ __align__(16) float sbl[D];
    ((float4*)sxl)[threadIdx.x] = ((const float4*)(g_xl + row * D))[threadIdx.x];
    ((float4*)sbl)[threadIdx.x] = ((const float4*)(g_bl + row * D))[threadIdx.x];
    __syncthreads();

    float c  = (float)(D - 1 - 2 * i);
    int   rm = D - 1 - i;
    float mx = fmaf(c, sxl[rm], -sbl[rm]);
    float num = sxl[rm], den = 1.f;
    const float T = 22.f;

    {
        int r = rm - 1;
        for (; r >= 3; r -= 4) {
            float t0 = fmaf(c, sxl[r],     -sbl[r])     - mx;
            float t1 = fmaf(c, sxl[r - 1], -sbl[r - 1]) - mx;
            float t2 = fmaf(c, sxl[r - 2], -sbl[r - 2]) - mx;
            float t3 = fmaf(c, sxl[r - 3], -sbl[r - 3]) - mx;
            float e0 = ex2f(t0), e1 = ex2f(t1), e2 = ex2f(t2), e3 = ex2f(t3);
            den += e0; num = fmaf(e0, sxl[r],     num);
            den += e1; num = fmaf(e1, sxl[r - 1], num);
            den += e2; num = fmaf(e2, sxl[r - 2], num);
            den += e3; num = fmaf(e3, sxl[r - 3], num);
            if (t3 < -T) { r = -1; break; }
        }
        for (; r >= 0; --r) {
            float t = fmaf(c, sxl[r], -sbl[r]) - mx;
            if (t < -T) break;
            float e = ex2f(t);
            den += e; num = fmaf(e, sxl[r], num);
        }
    }
    {
        int r = rm + 1;
        for (; r < D - 3; r += 4) {
            float t0 = fmaf(c, sxl[r],     -sbl[r])     - mx;
            float t1 = fmaf(c, sxl[r + 1], -sbl[r + 1]) - mx;
            float t2 = fmaf(c, sxl[r + 2], -sbl[r + 2]) - mx;
            float t3 = fmaf(c, sxl[r + 3], -sbl[r + 3]) - mx;
            float e0 = ex2f(t0), e1 = ex2f(t1), e2 = ex2f(t2), e3 = ex2f(t3);
            den += e0; num = fmaf(e0, sxl[r],     num);
            den += e1; num = fmaf(e1, sxl[r + 1], num);
            den += e2; num = fmaf(e2, sxl[r + 2], num);
            den += e3; num = fmaf(e3, sxl[r + 3], num);
            if (t3 < -T) { r = D; break; }
        }
        for (; r < D; ++r) {
            float t = fmaf(c, sxl[r], -sbl[r]) - mx;
            if (t < -T) break;
            float e = ex2f(t);
            den += e; num = fmaf(e, sxl[r], num);
        }
    }
    g_xs[row * D + i] = num * LN2 / den;
}

// ---------------- kernel 3: split-K GEMM (FFMA2, double-buffered) + fused combine ----
// grid (NTILES, KSPLIT), block 256. Tile 64m x 64n, K-slice 64, chunks of 16.
// A stored duplicated in smem so LDS.128 yields (a,a) f32x2 pairs.
__global__ void __launch_bounds__(256) gemm_fused_kernel(int layer,
                                                         const float* __restrict__ W,
                                                         const float* __restrict__ bias) {
    const float* A = (layer == 0) ? g_xs : g_h1;
    float*       H = (layer == 0) ? g_h1 : g_h2;
    int nt  = blockIdx.x;
    int ks  = blockIdx.y;
    int tid = threadIdx.x;
    int tx  = tid & 15;
    int ty  = tid >> 4;

    __shared__ __align__(16) float As[2][16][132];   // k x (2*m) duplicated
    __shared__ __align__(16) float Ws[2][16][68];    // k x n
    __shared__ int s_last;

    unsigned long long acc[4][2] = {};

    int m_ld = tid >> 2;           // 0..63
    int k4   = (tid & 3) << 2;     // 0,4,8,12
    const int kbase = ks * KSLICE;

    float4 av = *(const float4*)&A[m_ld * D + kbase + k4];
    float4 wv = *(const float4*)&W[(nt * 64 + m_ld) * D + kbase + k4];

#pragma unroll
    for (int j = 0; j < 4; j++) {
        float a = (j == 0) ? av.x : (j == 1) ? av.y : (j == 2) ? av.z : av.w;
        float w = (j == 0) ? wv.x : (j == 1) ? wv.y : (j == 2) ? wv.z : wv.w;
        *(float2*)&As[0][k4 + j][2 * m_ld] = make_float2(a, a);
        Ws[0][k4 + j][m_ld] = w;
    }
    __syncthreads();

#pragma unroll
    for (int c = 0; c < 4; c++) {
        int buf = c & 1;
        float4 av2, wv2;
        if (c < 3) {
            int kb = kbase + (c + 1) * 16;
            av2 = *(const float4*)&A[m_ld * D + kb + k4];
            wv2 = *(const float4*)&W[(nt * 64 + m_ld) * D + kb + k4];
        }
#pragma unroll
        for (int k = 0; k < 16; k++) {
            ulonglong2 a01 = *(const ulonglong2*)&As[buf][k][ty * 8];
            ulonglong2 a23 = *(const ulonglong2*)&As[buf][k][ty * 8 + 4];
            ulonglong2 b   = *(const ulonglong2*)&Ws[buf][k][tx * 4];
            ffma2(acc[0][0], a01.x, b.x); ffma2(acc[0][1], a01.x, b.y);
            ffma2(acc[1][0], a01.y, b.x); ffma2(acc[1][1], a01.y, b.y);
            ffma2(acc[2][0], a23.x, b.x); ffma2(acc[2][1], a23.x, b.y);
            ffma2(acc[3][0], a23.y, b.x); ffma2(acc[3][1], a23.y, b.y);
        }
        if (c < 3) {
            int nb = buf ^ 1;
#pragma unroll
            for (int j = 0; j < 4; j++) {
                float a = (j == 0) ? av2.x : (j == 1) ? av2.y : (j == 2) ? av2.z : av2.w;
                float w = (j == 0) ? wv2.x : (j == 1) ? wv2.y : (j == 2) ? wv2.z : wv2.w;
                *(float2*)&As[nb][k4 + j][2 * m_ld] = make_float2(a, a);
                Ws[nb][k4 + j][m_ld] = w;
            }
            __syncthreads();
        }
    }

#pragma unroll
    for (int i = 0; i < 4; i++) {
        int m = (ty << 2) + i;
        ulonglong2 v;
        v.x = acc[i][0]; v.y = acc[i][1];
        *(ulonglong2*)&g_part[(ks * BATCH + m) * D + nt * 64 + (tx << 2)] = v;
    }

    // ---- election: last block for this n-tile does the combine ----
    __syncthreads();
    __threadfence();
    if (tid == 0) {
        unsigned old = atomicAdd(&g_cnt[layer][nt], 1u);
        s_last = (old == KSPLIT - 1);
        if (s_last) g_cnt[layer][nt] = 0;
    }
    __syncthreads();
    if (!s_last) return;
    __threadfence();

#pragma unroll
    for (int t = 0; t < 4; t++) {
        int idx = t * 256 + tid;
        int m   = idx >> 4;
        int c4  = idx & 15;
        int f4  = m * (D / 4) + nt * 16 + c4;
        float4 s = ((const float4*)g_part)[(0 * BATCH + m) * (D / 4) + nt * 16 + c4];
#pragma unroll
        for (int k = 1; k < KSPLIT; k++) {
            float4 v = ((const float4*)g_part)[(k * BATCH + m) * (D / 4) + nt * 16 + c4];
            s.x += v.x; s.y += v.y; s.z += v.z; s.w += v.w;
        }
        float4 bv = ((const float4*)bias)[nt * 16 + c4];
        s.x += bv.x; s.y += bv.y; s.z += bv.z; s.w += bv.w;
        s.x = (s.x >= 0.f) ? s.x : 0.01f * s.x;
        s.y = (s.y >= 0.f) ? s.y : 0.01f * s.y;
        s.z = (s.z >= 0.f) ? s.z : 0.01f * s.z;
        s.w = (s.w >= 0.f) ? s.w : 0.01f * s.w;
        ((float4*)H)[f4] = s;
    }
}

// ---------------- kernel 4: final 1024 -> 2 head ----------------
__global__ void __launch_bounds__(256) final_kernel(const float* __restrict__ W3,
                                                    const float* __restrict__ b3,
                                                    float* __restrict__ out) {
    int b   = blockIdx.x;
    int tid = threadIdx.x;
    int c   = tid >> 7;
    int j0  = tid & 127;
    float acc = 0.f;
#pragma unroll
    for (int t = 0; t < 8; t++) {
        int j = j0 + (t << 7);
        acc = fmaf(g_h2[b * D + j], W3[c * D + j], acc);
    }
    __shared__ float red[8];
#pragma unroll
    for (int off = 16; off; off >>= 1)
        acc += __shfl_down_sync(0xffffffffu, acc, off);
    if ((tid & 31) == 0) red[tid >> 5] = acc;
    __syncthreads();
    if (tid < 2) {
        float s = (red[tid * 4] + red[tid * 4 + 1]) +
                  (red[tid * 4 + 2] + red[tid * 4 + 3]);
        out[b * 2 + tid] = s + b3[tid];
    }
}

extern "C" void kernel_launch(void* const* d_in, const int* in_sizes, int n_in,
                              void* d_out, int out_size) {
    const float* x  = (const float*)d_in[0];
    const float* W1 = (const float*)d_in[1];
    const float* b1 = (const float*)d_in[2];
    const float* W2 = (const float*)d_in[3];
    const float* b2 = (const float*)d_in[4];
    const float* W3 = (const float*)d_in[5];
    const float* b3 = (const float*)d_in[6];
    float* out = (float*)d_out;
    (void)in_sizes; (void)n_in; (void)out_size;

    sort_kernel<<<BATCH, D>>>(x);
    softsort_kernel<<<dim3(D / 256, BATCH), 256>>>();
    gemm_fused_kernel<<<dim3(NTILES, KSPLIT), 256>>>(0, W1, b1);
    gemm_fused_kernel<<<dim3(NTILES, KSPLIT), 256>>>(1, W2, b2);
    final_kernel<<<BATCH, 256>>>(W3, b3, out);
}

// round 5
// speedup vs baseline: 1.0532x; 1.0532x over previous
#include <cuda_runtime.h>

#define D      1024
#define BATCH  64
#define KSPLIT 16
#define KSLICE (D / KSPLIT)      // 64
#define NTILES (D / 64)          // 16
#define LOG2E  1.4426950408889634f
#define LN2    0.6931471805599453f

// ---------------- scratch (no allocations allowed) ----------------
__device__ __align__(16) float g_xl[BATCH * D];
__device__ __align__(16) float g_bl[BATCH * D];
__device__ __align__(16) float g_xs[BATCH * D];
__device__ __align__(16) float g_h1[BATCH * D];
__device__ __align__(16) float g_h2[BATCH * D];
__device__ __align__(16) float g_part[KSPLIT * BATCH * D];
__device__ unsigned g_cnt[2][NTILES];

__device__ __forceinline__ float ex2f(float x) {
    float r;
    asm("ex2.approx.ftz.f32 %0, %1;" : "=f"(r) : "f"(x));
    return r;
}

__device__ __forceinline__ void ffma2(unsigned long long& acc,
                                      unsigned long long a,
                                      unsigned long long b) {
    asm("fma.rn.f32x2 %0, %1, %2, %3;" : "=l"(acc) : "l"(a), "l"(b), "l"(acc));
}

__device__ __forceinline__ unsigned long long dup2(float v) {
    unsigned long long r;
    asm("mov.b64 %0, {%1, %1};" : "=l"(r) : "f"(v));
    return r;
}

// ---------------- kernel 1: per-row bitonic sort + prefix-sum Bsum ----------------
__global__ void __launch_bounds__(D) sort_kernel(const float* __restrict__ x) {
    int row = blockIdx.x;
    int tid = threadIdx.x;
    __shared__ __align__(16) float sv[D];
    __shared__ float wsum[32];

    sv[tid] = x[row * D + tid];
    __syncthreads();

    for (int k = 2; k <= D; k <<= 1) {
        for (int j = k >> 1; j > 0; j >>= 1) {
            int ixj = tid ^ j;
            if (ixj > tid) {
                float a = sv[tid], b = sv[ixj];
                bool up = ((tid & k) == 0);
                if ((a > b) == up) { sv[tid] = b; sv[ixj] = a; }
            }
            __syncthreads();
        }
    }

    float v = sv[tid];
    int lane = tid & 31, wid = tid >> 5;
    float p = v;
#pragma unroll
    for (int off = 1; off < 32; off <<= 1) {
        float n = __shfl_up_sync(0xffffffffu, p, off);
        if (lane >= off) p += n;
    }
    if (lane == 31) wsum[wid] = p;
    __syncthreads();
    if (wid == 0) {
        float w = wsum[lane];
#pragma unroll
        for (int off = 1; off < 32; off <<= 1) {
            float n = __shfl_up_sync(0xffffffffu, w, off);
            if (lane >= off) w += n;
        }
        wsum[lane] = w;
    }
    __syncthreads();
    float S    = wsum[31];
    float pinc = p + (wid ? wsum[wid - 1] : 0.f);
    float bs   = (float)(2 * tid - D) * v + S - 2.f * (pinc - v);
    g_xl[row * D + tid] = v * LOG2E;
    g_bl[row * D + tid] = bs * LOG2E;
}

// ---------------- kernel 2: windowed soft-sort, unroll-4 ----------------
__global__ void __launch_bounds__(256) softsort_kernel() {
    int row = blockIdx.y;
    int i   = blockIdx.x * blockDim.x + threadIdx.x;
    __shared__ __align__(16) float sxl[D];
    __shared__ __align__(16) float sbl[D];
    ((float4*)sxl)[threadIdx.x] = ((const float4*)(g_xl + row * D))[threadIdx.x];
    ((float4*)sbl)[threadIdx.x] = ((const float4*)(g_bl + row * D))[threadIdx.x];
    __syncthreads();

    float c  = (float)(D - 1 - 2 * i);
    int   rm = D - 1 - i;
    float mx = fmaf(c, sxl[rm], -sbl[rm]);
    float num = sxl[rm], den = 1.f;
    const float T = 22.f;

    {
        int r = rm - 1;
        for (; r >= 3; r -= 4) {
            float t0 = fmaf(c, sxl[r],     -sbl[r])     - mx;
            float t1 = fmaf(c, sxl[r - 1], -sbl[r - 1]) - mx;
            float t2 = fmaf(c, sxl[r - 2], -sbl[r - 2]) - mx;
            float t3 = fmaf(c, sxl[r - 3], -sbl[r - 3]) - mx;
            float e0 = ex2f(t0), e1 = ex2f(t1), e2 = ex2f(t2), e3 = ex2f(t3);
            den += e0; num = fmaf(e0, sxl[r],     num);
            den += e1; num = fmaf(e1, sxl[r - 1], num);
            den += e2; num = fmaf(e2, sxl[r - 2], num);
            den += e3; num = fmaf(e3, sxl[r - 3], num);
            if (t3 < -T) { r = -1; break; }
        }
        for (; r >= 0; --r) {
            float t = fmaf(c, sxl[r], -sbl[r]) - mx;
            if (t < -T) break;
            float e = ex2f(t);
            den += e; num = fmaf(e, sxl[r], num);
        }
    }
    {
        int r = rm + 1;
        for (; r < D - 3; r += 4) {
            float t0 = fmaf(c, sxl[r],     -sbl[r])     - mx;
            float t1 = fmaf(c, sxl[r + 1], -sbl[r + 1]) - mx;
            float t2 = fmaf(c, sxl[r + 2], -sbl[r + 2]) - mx;
            float t3 = fmaf(c, sxl[r + 3], -sbl[r + 3]) - mx;
            float e0 = ex2f(t0), e1 = ex2f(t1), e2 = ex2f(t2), e3 = ex2f(t3);
            den += e0; num = fmaf(e0, sxl[r],     num);
            den += e1; num = fmaf(e1, sxl[r + 1], num);
            den += e2; num = fmaf(e2, sxl[r + 2], num);
            den += e3; num = fmaf(e3, sxl[r + 3], num);
            if (t3 < -T) { r = D; break; }
        }
        for (; r < D; ++r) {
            float t = fmaf(c, sxl[r], -sbl[r]) - mx;
            if (t < -T) break;
            float e = ex2f(t);
            den += e; num = fmaf(e, sxl[r], num);
        }
    }
    g_xs[row * D + i] = num * LN2 / den;
}

// ---------------- kernel 3: split-K GEMM + fused combine ----------------
// A smem transposed [k][m] -> natural (m,m+1) f32x2 pairs, one LDS.128 = 2 pairs.
// B duplicated in registers (mov.b64 {b,b}) on the idle ALU pipe.
// Inner loop per k: 2 LDS.128 + 4 ALU + 8 FFMA2.
__global__ void __launch_bounds__(256) gemm_fused_kernel(int layer,
                                                         const float* __restrict__ W,
                                                         const float* __restrict__ bias) {
    const float* A = (layer == 0) ? g_xs : g_h1;
    float*       H = (layer == 0) ? g_h1 : g_h2;
    int nt  = blockIdx.x;
    int ks  = blockIdx.y;
    int tid = threadIdx.x;
    int tx  = tid & 15;            // n group (4n)
    int ty  = tid >> 4;            // m group (4m)

    __shared__ __align__(16) float As[2][16][68];   // [k][m] transposed
    __shared__ __align__(16) float Ws[2][16][68];   // [k][n]
    __shared__ int s_last;

    unsigned long long acc[2][4] = {};   // [m-pair][n]

    int r_ld = tid >> 2;           // 0..63
    int k4   = (tid & 3) << 2;     // 0,4,8,12
    const int kbase = ks * KSLICE;

    float4 av = *(const float4*)&A[r_ld * D + kbase + k4];
    float4 wv = *(const float4*)&W[(nt * 64 + r_ld) * D + kbase + k4];
    As[0][k4 + 0][r_ld] = av.x; As[0][k4 + 1][r_ld] = av.y;
    As[0][k4 + 2][r_ld] = av.z; As[0][k4 + 3][r_ld] = av.w;
    Ws[0][k4 + 0][r_ld] = wv.x; Ws[0][k4 + 1][r_ld] = wv.y;
    Ws[0][k4 + 2][r_ld] = wv.z; Ws[0][k4 + 3][r_ld] = wv.w;
    __syncthreads();

#pragma unroll
    for (int c = 0; c < 4; c++) {
        int buf = c & 1;
        float4 av2, wv2;
        if (c < 3) {
            int kb = kbase + (c + 1) * 16;
            av2 = *(const float4*)&A[r_ld * D + kb + k4];
            wv2 = *(const float4*)&W[(nt * 64 + r_ld) * D + kb + k4];
        }
#pragma unroll
        for (int k = 0; k < 16; k++) {
            ulonglong2 la = *(const ulonglong2*)&As[buf][k][ty * 4];  // (m0,m1),(m2,m3)
            float4     bv = *(const float4*)&Ws[buf][k][tx * 4];
            unsigned long long b0 = dup2(bv.x);
            unsigned long long b1 = dup2(bv.y);
            unsigned long long b2 = dup2(bv.z);
            unsigned long long b3 = dup2(bv.w);
            ffma2(acc[0][0], la.x, b0); ffma2(acc[1][0], la.y, b0);
            ffma2(acc[0][1], la.x, b1); ffma2(acc[1][1], la.y, b1);
            ffma2(acc[0][2], la.x, b2); ffma2(acc[1][2], la.y, b2);
            ffma2(acc[0][3], la.x, b3); ffma2(acc[1][3], la.y, b3);
        }
        if (c < 3) {
            int nb = buf ^ 1;
            As[nb][k4 + 0][r_ld] = av2.x; As[nb][k4 + 1][r_ld] = av2.y;
            As[nb][k4 + 2][r_ld] = av2.z; As[nb][k4 + 3][r_ld] = av2.w;
            Ws[nb][k4 + 0][r_ld] = wv2.x; Ws[nb][k4 + 1][r_ld] = wv2.y;
            Ws[nb][k4 + 2][r_ld] = wv2.z; Ws[nb][k4 + 3][r_ld] = wv2.w;
            __syncthreads();
        }
    }

    // unpack: acc[p][n] lanes = (m = ty*4+2p, m+1)
#pragma unroll
    for (int p = 0; p < 2; p++) {
        unsigned lo0, hi0, lo1, hi1, lo2, hi2, lo3, hi3;
        asm("mov.b64 {%0,%1}, %2;" : "=r"(lo0), "=r"(hi0) : "l"(acc[p][0]));
        asm("mov.b64 {%0,%1}, %2;" : "=r"(lo1), "=r"(hi1) : "l"(acc[p][1]));
        asm("mov.b64 {%0,%1}, %2;" : "=r"(lo2), "=r"(hi2) : "l"(acc[p][2]));
        asm("mov.b64 {%0,%1}, %2;" : "=r"(lo3), "=r"(hi3) : "l"(acc[p][3]));
        int m0 = ty * 4 + 2 * p;
        float4 v0 = make_float4(__uint_as_float(lo0), __uint_as_float(lo1),
                                __uint_as_float(lo2), __uint_as_float(lo3));
        float4 v1 = make_float4(__uint_as_float(hi0), __uint_as_float(hi1),
                                __uint_as_float(hi2), __uint_as_float(hi3));
        *(float4*)&g_part[(ks * BATCH + m0)     * D + nt * 64 + (tx << 2)] = v0;
        *(float4*)&g_part[(ks * BATCH + m0 + 1) * D + nt * 64 + (tx << 2)] = v1;
    }

    // ---- election: last block for this n-tile does the combine ----
    __syncthreads();
    __threadfence();
    if (tid == 0) {
        unsigned old = atomicAdd(&g_cnt[layer][nt], 1u);
        s_last = (old == KSPLIT - 1);
        if (s_last) g_cnt[layer][nt] = 0;
    }
    __syncthreads();
    if (!s_last) return;
    __threadfence();

#pragma unroll
    for (int t = 0; t < 4; t++) {
        int idx = t * 256 + tid;
        int m   = idx >> 4;
        int c4  = idx & 15;
        int f4  = m * (D / 4) + nt * 16 + c4;
        float4 s = ((const float4*)g_part)[(0 * BATCH + m) * (D / 4) + nt * 16 + c4];
#pragma unroll
        for (int k = 1; k < KSPLIT; k++) {
            float4 v = ((const float4*)g_part)[(k * BATCH + m) * (D / 4) + nt * 16 + c4];
            s.x += v.x; s.y += v.y; s.z += v.z; s.w += v.w;
        }
        float4 bv = ((const float4*)bias)[nt * 16 + c4];
        s.x += bv.x; s.y += bv.y; s.z += bv.z; s.w += bv.w;
        s.x = (s.x >= 0.f) ? s.x : 0.01f * s.x;
        s.y = (s.y >= 0.f) ? s.y : 0.01f * s.y;
        s.z = (s.z >= 0.f) ? s.z : 0.01f * s.z;
        s.w = (s.w >= 0.f) ? s.w : 0.01f * s.w;
        ((float4*)H)[f4] = s;
    }
}

// ---------------- kernel 4: final 1024 -> 2 head ----------------
__global__ void __launch_bounds__(256) final_kernel(const float* __restrict__ W3,
                                                    const float* __restrict__ b3,
                                                    float* __restrict__ out) {
    int b   = blockIdx.x;
    int tid = threadIdx.x;
    int c   = tid >> 7;
    int j0  = tid & 127;
    float acc = 0.f;
#pragma unroll
    for (int t = 0; t < 8; t++) {
        int j = j0 + (t << 7);
        acc = fmaf(g_h2[b * D + j], W3[c * D + j], acc);
    }
    __shared__ float red[8];
#pragma unroll
    for (int off = 16; off; off >>= 1)
        acc += __shfl_down_sync(0xffffffffu, acc, off);
    if ((tid & 31) == 0) red[tid >> 5] = acc;
    __syncthreads();
    if (tid < 2) {
        float s = (red[tid * 4] + red[tid * 4 + 1]) +
                  (red[tid * 4 + 2] + red[tid * 4 + 3]);
        out[b * 2 + tid] = s + b3[tid];
    }
}

extern "C" void kernel_launch(void* const* d_in, const int* in_sizes, int n_in,
                              void* d_out, int out_size) {
    const float* x  = (const float*)d_in[0];
    const float* W1 = (const float*)d_in[1];
    const float* b1 = (const float*)d_in[2];
    const float* W2 = (const float*)d_in[3];
    const float* b2 = (const float*)d_in[4];
    const float* W3 = (const float*)d_in[5];
    const float* b3 = (const float*)d_in[6];
    float* out = (float*)d_out;
    (void)in_sizes; (void)n_in; (void)out_size;

    sort_kernel<<<BATCH, D>>>(x);
    softsort_kernel<<<dim3(D / 256, BATCH), 256>>>();
    gemm_fused_kernel<<<dim3(NTILES, KSPLIT), 256>>>(0, W1, b1);
    gemm_fused_kernel<<<dim3(NTILES, KSPLIT), 256>>>(1, W2, b2);
    final_kernel<<<BATCH, 256>>>(W3, b3, out);
}